// round 3
// baseline (speedup 1.0000x reference)
#include <cuda_runtime.h>
#include <cstdint>
#include <math.h>

// Problem constants
#define BATCH 4
#define SQ    4096
#define DD    256

// Scratch QKV buffers (static __device__ arrays: allocation-free rule)
__device__ float g_Q[(size_t)BATCH * SQ * DD];
__device__ float g_K[(size_t)BATCH * SQ * DD];
__device__ float g_V[(size_t)BATCH * SQ * DD];

// ---------------------------------------------------------------------------
// helpers
// ---------------------------------------------------------------------------
static __device__ __forceinline__ uint32_t f2tf32u(float f) {
    uint32_t u;
    asm("cvt.rna.tf32.f32 %0, %1;" : "=r"(u) : "f"(f));
    return u;
}
static __device__ __forceinline__ float tf32r(float f) {
    return __uint_as_float(f2tf32u(f));
}

// D += A(16x8,row) * B(8x8,col) tf32
static __device__ __forceinline__ void mma8(float c[4], const uint32_t a[4], const uint32_t b[2]) {
    asm volatile(
        "mma.sync.aligned.m16n8k8.row.col.f32.tf32.tf32.f32 "
        "{%0,%1,%2,%3}, {%4,%5,%6,%7}, {%8,%9}, {%0,%1,%2,%3};\n"
        : "+f"(c[0]), "+f"(c[1]), "+f"(c[2]), "+f"(c[3])
        : "r"(a[0]), "r"(a[1]), "r"(a[2]), "r"(a[3]), "r"(b[0]), "r"(b[1]));
}

// ---------------------------------------------------------------------------
// Kernel 1: QKV projection, split-tf32 (3-term) for ~fp32-accurate Q/K/V.
// Y[m, n] = sum_d x[m,d] * W[n,d] + b[n], output rounded to tf32.
// Grid: (16384/64, 256/64, 3), 128 threads.
// smem: Xhi/Xlo/Whi/Wlo each [64][68] floats = 69632 B
// ---------------------------------------------------------------------------
__global__ void __launch_bounds__(128, 1)
proj_kernel(const float* __restrict__ x,
            const float* __restrict__ Wq, const float* __restrict__ bq,
            const float* __restrict__ Wk, const float* __restrict__ bk,
            const float* __restrict__ Wv, const float* __restrict__ bv)
{
    extern __shared__ float sm[];
    float* Xh = sm;
    float* Xl = Xh + 64 * 68;
    float* Wh = Xl + 64 * 68;
    float* Wl = Wh + 64 * 68;

    const int tid  = threadIdx.x;
    const int lane = tid & 31;
    const int wid  = tid >> 5;
    const int grp  = lane >> 2;
    const int tig  = lane & 3;

    const int m0 = blockIdx.x * 64;
    const int n0 = blockIdx.y * 64;
    const int w  = blockIdx.z;

    const float* W    = (w == 0) ? Wq : ((w == 1) ? Wk : Wv);
    const float* bias = (w == 0) ? bq : ((w == 1) ? bk : bv);
    float* outp       = (w == 0) ? g_Q : ((w == 1) ? g_K : g_V);

    float sc[8][4];
#pragma unroll
    for (int n = 0; n < 8; n++) { sc[n][0] = 0.f; sc[n][1] = 0.f; sc[n][2] = 0.f; sc[n][3] = 0.f; }

    for (int kc = 0; kc < 256; kc += 64) {
        __syncthreads();
        // load + split 64x64 chunks of X and W
        for (int i = tid; i < 1024; i += 128) {
            const int r = i >> 4;
            const int c = (i & 15) << 2;
            float4 xv = *reinterpret_cast<const float4*>(x + (size_t)(m0 + r) * 256 + kc + c);
            float4 wv = *reinterpret_cast<const float4*>(W + (size_t)(n0 + r) * 256 + kc + c);
            const int o = r * 68 + c;
            float h;
            h = tf32r(xv.x); Xh[o+0] = h; Xl[o+0] = tf32r(xv.x - h);
            h = tf32r(xv.y); Xh[o+1] = h; Xl[o+1] = tf32r(xv.y - h);
            h = tf32r(xv.z); Xh[o+2] = h; Xl[o+2] = tf32r(xv.z - h);
            h = tf32r(xv.w); Xh[o+3] = h; Xl[o+3] = tf32r(xv.w - h);
            h = tf32r(wv.x); Wh[o+0] = h; Wl[o+0] = tf32r(wv.x - h);
            h = tf32r(wv.y); Wh[o+1] = h; Wl[o+1] = tf32r(wv.y - h);
            h = tf32r(wv.z); Wh[o+2] = h; Wl[o+2] = tf32r(wv.z - h);
            h = tf32r(wv.w); Wh[o+3] = h; Wl[o+3] = tf32r(wv.w - h);
        }
        __syncthreads();

        const float* xr = Xh + (wid * 16 + grp) * 68;
        const float* xlr = Xl + (wid * 16 + grp) * 68;
#pragma unroll
        for (int kk = 0; kk < 64; kk += 8) {
            uint32_t ah[4], al[4];
            ah[0] = __float_as_uint(xr[kk + tig]);
            ah[1] = __float_as_uint(xr[8 * 68 + kk + tig]);
            ah[2] = __float_as_uint(xr[kk + tig + 4]);
            ah[3] = __float_as_uint(xr[8 * 68 + kk + tig + 4]);
            al[0] = __float_as_uint(xlr[kk + tig]);
            al[1] = __float_as_uint(xlr[8 * 68 + kk + tig]);
            al[2] = __float_as_uint(xlr[kk + tig + 4]);
            al[3] = __float_as_uint(xlr[8 * 68 + kk + tig + 4]);
#pragma unroll
            for (int n = 0; n < 8; n++) {
                const int wro = (n * 8 + grp) * 68 + kk + tig;
                uint32_t bh[2], bl[2];
                bh[0] = __float_as_uint(Wh[wro]);
                bh[1] = __float_as_uint(Wh[wro + 4]);
                bl[0] = __float_as_uint(Wl[wro]);
                bl[1] = __float_as_uint(Wl[wro + 4]);
                mma8(sc[n], ah, bh);
                mma8(sc[n], al, bh);
                mma8(sc[n], ah, bl);
            }
        }
    }

    // epilogue: + bias, round to tf32, store
    const int r0 = m0 + wid * 16 + grp;
    const int r1 = r0 + 8;
#pragma unroll
    for (int n = 0; n < 8; n++) {
        const int c = n0 + n * 8 + 2 * tig;
        const float b0 = __ldg(bias + c);
        const float b1 = __ldg(bias + c + 1);
        outp[(size_t)r0 * 256 + c]     = tf32r(sc[n][0] + b0);
        outp[(size_t)r0 * 256 + c + 1] = tf32r(sc[n][1] + b1);
        outp[(size_t)r1 * 256 + c]     = tf32r(sc[n][2] + b0);
        outp[(size_t)r1 * 256 + c + 1] = tf32r(sc[n][3] + b1);
    }
}

// ---------------------------------------------------------------------------
// Kernel 2: flash attention with exact periodic bias.
// Block: one (batch, 64-row q tile). 128 threads (4 warps), warp owns 16 rows.
// KV tiles of 64 keys staged in smem. TF32 mma for QK^T and P*V; fp32 softmax.
// smem: Qs[64][260] Ks[64][260] Vs[64][260] Ps[64][68] t720[720] t24[24]
//       = 55016 floats = 220064 B
// ---------------------------------------------------------------------------
__global__ void __launch_bounds__(128, 1)
flash_kernel(const float* __restrict__ beta, float* __restrict__ out)
{
    extern __shared__ float sm[];
    float* Qs   = sm;
    float* Ks   = Qs + 64 * 260;
    float* Vs   = Ks + 64 * 260;
    float* Ps   = Vs + 64 * 260;
    float* t720 = Ps + 64 * 68;
    float* t24  = t720 + 720;

    const int tid  = threadIdx.x;
    const int lane = tid & 31;
    const int wid  = tid >> 5;
    const int grp  = lane >> 2;
    const int tig  = lane & 3;

    const int q0 = blockIdx.x * 64;
    const int b  = blockIdx.y;

    // bias tables (exact fp32, same periodic values as reference)
    {
        const float be0 = __ldg(beta + 0);
        const float be1 = __ldg(beta + 1);
        const float twopi = 6.28318530717958647692f;
        for (int t = tid; t < 720; t += 128)
            t720[t] = be1 * cosf(twopi * (float)t / 720.0f);
        if (tid < 24)
            t24[tid] = be0 * cosf(twopi * (float)tid / 24.0f);
    }

    const float* Qg = g_Q + ((size_t)b * SQ + q0) * DD;
    const float* Kg = g_K + (size_t)b * SQ * DD;
    const float* Vg = g_V + (size_t)b * SQ * DD;

    // load Q tile
    for (int i = tid; i < 64 * 64; i += 128) {
        const int r = i >> 6;
        const int c = (i & 63) << 2;
        *reinterpret_cast<float4*>(Qs + r * 260 + c) =
            *reinterpret_cast<const float4*>(Qg + (size_t)r * 256 + c);
    }

    float m0 = -INFINITY, m1 = -INFINITY, l0 = 0.f, l1 = 0.f;
    float o[32][4];
#pragma unroll
    for (int n = 0; n < 32; n++) { o[n][0] = 0.f; o[n][1] = 0.f; o[n][2] = 0.f; o[n][3] = 0.f; }

    const float* qr = Qs + (wid * 16 + grp) * 260;
    const float* pr = Ps + (wid * 16 + grp) * 68;
    const int i0 = q0 + wid * 16 + grp;
    const int i1 = i0 + 8;

#pragma unroll 1
    for (int kv = 0; kv < 64; kv++) {
        __syncthreads();
        {
            const float* kgp = Kg + (size_t)kv * 64 * 256;
            const float* vgp = Vg + (size_t)kv * 64 * 256;
            for (int i = tid; i < 64 * 64; i += 128) {
                const int r = i >> 6;
                const int c = (i & 63) << 2;
                *reinterpret_cast<float4*>(Ks + r * 260 + c) =
                    *reinterpret_cast<const float4*>(kgp + (size_t)r * 256 + c);
                *reinterpret_cast<float4*>(Vs + r * 260 + c) =
                    *reinterpret_cast<const float4*>(vgp + (size_t)r * 256 + c);
            }
        }
        __syncthreads();

        // ---- S = Q * K^T (per-warp 16x64) ----
        float sc[8][4];
#pragma unroll
        for (int n = 0; n < 8; n++) { sc[n][0] = 0.f; sc[n][1] = 0.f; sc[n][2] = 0.f; sc[n][3] = 0.f; }

#pragma unroll 4
        for (int kk = 0; kk < 256; kk += 8) {
            uint32_t a[4];
            a[0] = __float_as_uint(qr[kk + tig]);
            a[1] = __float_as_uint(qr[8 * 260 + kk + tig]);
            a[2] = __float_as_uint(qr[kk + tig + 4]);
            a[3] = __float_as_uint(qr[8 * 260 + kk + tig + 4]);
#pragma unroll
            for (int n = 0; n < 8; n++) {
                const int ko = (n * 8 + grp) * 260 + kk + tig;
                uint32_t bb[2];
                bb[0] = __float_as_uint(Ks[ko]);
                bb[1] = __float_as_uint(Ks[ko + 4]);
                mma8(sc[n], a, bb);
            }
        }

        // ---- scale + periodic bias, row max ----
        const int jb = kv * 64;
        float rm0 = -INFINITY, rm1 = -INFINITY;
#pragma unroll
        for (int n = 0; n < 8; n++) {
            const int j0 = jb + n * 8 + 2 * tig;
            const int j1 = j0 + 1;
            const int d00 = abs(i0 - j0), d01 = abs(i0 - j1);
            const int d10 = abs(i1 - j0), d11 = abs(i1 - j1);
            sc[n][0] = sc[n][0] * 0.0625f + t24[d00 % 24] + t720[d00 % 720];
            sc[n][1] = sc[n][1] * 0.0625f + t24[d01 % 24] + t720[d01 % 720];
            sc[n][2] = sc[n][2] * 0.0625f + t24[d10 % 24] + t720[d10 % 720];
            sc[n][3] = sc[n][3] * 0.0625f + t24[d11 % 24] + t720[d11 % 720];
            rm0 = fmaxf(rm0, fmaxf(sc[n][0], sc[n][1]));
            rm1 = fmaxf(rm1, fmaxf(sc[n][2], sc[n][3]));
        }
        rm0 = fmaxf(rm0, __shfl_xor_sync(0xffffffffu, rm0, 1));
        rm0 = fmaxf(rm0, __shfl_xor_sync(0xffffffffu, rm0, 2));
        rm1 = fmaxf(rm1, __shfl_xor_sync(0xffffffffu, rm1, 1));
        rm1 = fmaxf(rm1, __shfl_xor_sync(0xffffffffu, rm1, 2));

        const float m0n = fmaxf(m0, rm0);
        const float m1n = fmaxf(m1, rm1);
        const float c0 = __expf(m0 - m0n);
        const float c1 = __expf(m1 - m1n);

        // ---- P = exp(S - m), store tf32-rounded to smem ----
        float rs0 = 0.f, rs1 = 0.f;
        float* pw0 = Ps + (wid * 16 + grp) * 68 + 2 * tig;
        float* pw1 = pw0 + 8 * 68;
#pragma unroll
        for (int n = 0; n < 8; n++) {
            const float p00 = __expf(sc[n][0] - m0n);
            const float p01 = __expf(sc[n][1] - m0n);
            const float p10 = __expf(sc[n][2] - m1n);
            const float p11 = __expf(sc[n][3] - m1n);
            rs0 += p00 + p01;
            rs1 += p10 + p11;
            pw0[n * 8]     = tf32r(p00);
            pw0[n * 8 + 1] = tf32r(p01);
            pw1[n * 8]     = tf32r(p10);
            pw1[n * 8 + 1] = tf32r(p11);
        }
        rs0 += __shfl_xor_sync(0xffffffffu, rs0, 1);
        rs0 += __shfl_xor_sync(0xffffffffu, rs0, 2);
        rs1 += __shfl_xor_sync(0xffffffffu, rs1, 1);
        rs1 += __shfl_xor_sync(0xffffffffu, rs1, 2);

        l0 = l0 * c0 + rs0;
        l1 = l1 * c1 + rs1;
        m0 = m0n;
        m1 = m1n;

#pragma unroll
        for (int n = 0; n < 32; n++) {
            o[n][0] *= c0; o[n][1] *= c0; o[n][2] *= c1; o[n][3] *= c1;
        }
        __syncwarp();

        // ---- O += P * V (per-warp 16x256) ----
#pragma unroll
        for (int kk = 0; kk < 64; kk += 8) {
            uint32_t a[4];
            a[0] = __float_as_uint(pr[kk + tig]);
            a[1] = __float_as_uint(pr[8 * 68 + kk + tig]);
            a[2] = __float_as_uint(pr[kk + tig + 4]);
            a[3] = __float_as_uint(pr[8 * 68 + kk + tig + 4]);
            const float* vb0 = Vs + (kk + tig) * 260 + grp;
            const float* vb1 = Vs + (kk + tig + 4) * 260 + grp;
#pragma unroll
            for (int n = 0; n < 32; n++) {
                uint32_t bb[2];
                bb[0] = __float_as_uint(vb0[n * 8]);
                bb[1] = __float_as_uint(vb1[n * 8]);
                mma8(o[n], a, bb);
            }
        }
    }

    // ---- write output ----
    const float inv0 = 1.0f / l0;
    const float inv1 = 1.0f / l1;
    float* og = out + (size_t)b * SQ * DD;
#pragma unroll
    for (int n = 0; n < 32; n++) {
        const int c = n * 8 + 2 * tig;
        og[(size_t)i0 * 256 + c]     = o[n][0] * inv0;
        og[(size_t)i0 * 256 + c + 1] = o[n][1] * inv0;
        og[(size_t)i1 * 256 + c]     = o[n][2] * inv1;
        og[(size_t)i1 * 256 + c + 1] = o[n][3] * inv1;
    }
}

// ---------------------------------------------------------------------------
extern "C" void kernel_launch(void* const* d_in, const int* in_sizes, int n_in,
                              void* d_out, int out_size)
{
    const float* x    = (const float*)d_in[0];
    const float* Wq   = (const float*)d_in[1];
    const float* bq   = (const float*)d_in[2];
    const float* Wk   = (const float*)d_in[3];
    const float* bk   = (const float*)d_in[4];
    const float* Wv   = (const float*)d_in[5];
    const float* bv   = (const float*)d_in[6];
    const float* beta = (const float*)d_in[7];
    float* out = (float*)d_out;

    const int PROJ_SMEM  = 4 * 64 * 68 * 4;                  // 69632
    const int FLASH_SMEM = (3 * 64 * 260 + 64 * 68 + 744) * 4; // 220064

    cudaFuncSetAttribute(proj_kernel, cudaFuncAttributeMaxDynamicSharedMemorySize, PROJ_SMEM);
    cudaFuncSetAttribute(flash_kernel, cudaFuncAttributeMaxDynamicSharedMemorySize, FLASH_SMEM);

    proj_kernel<<<dim3(256, 4, 3), 128, PROJ_SMEM>>>(x, Wq, bq, Wk, bk, Wv, bv);
    flash_kernel<<<dim3(64, 4), 128, FLASH_SMEM>>>(beta, out);
}